// round 4
// baseline (speedup 1.0000x reference)
#include <cuda_runtime.h>
#include <math.h>

#define D_MODEL 2048
#define NH      16
#define DKH     128
#define BATCH   2
#define SEQ     2048
#define MTOT    (BATCH*SEQ)   // 4096

// Scratch (allocation-free rule: __device__ globals)
__device__ float g_Q[(size_t)BATCH*NH*SEQ*DKH];
__device__ float g_K[(size_t)BATCH*NH*SEQ*DKH];
__device__ float g_V[(size_t)BATCH*NH*SEQ*DKH];
__device__ float g_AO[(size_t)MTOT*D_MODEL];

// ---------------------------------------------------------------------------
// GEMM: C[m,n] = sum_k A[m,k] * B[n,k]   (A row-major [M,K], B row-major [N,K])
// BM=BN=128, BK=16, 256 threads, 8x8 micro-tile (split 4+4 to stay
// conflict-free), double-buffered smem, register prefetch of the next tile.
// SCATTER=1: write into [b, h, s, d] layout. With BN=128 each n-tile is
// exactly one head.
// ---------------------------------------------------------------------------
template<int SCATTER>
__global__ __launch_bounds__(256) void gemm_abt_kernel(
    const float* __restrict__ A, const float* __restrict__ B,
    float* __restrict__ C, int M, int N, int K)
{
    constexpr int BM = 128, BN = 128, BK = 16;
    __shared__ float As[2][BK][BM];   // 16 KB
    __shared__ float Bs[2][BK][BN];   // 16 KB

    const int tid = threadIdx.x;
    const int tx = tid & 15, ty = tid >> 4;
    const int m0 = blockIdx.y * BM, n0 = blockIdx.x * BN;

    // Global-load mapping: each thread owns one row and 8 contiguous k.
    const int lrow = tid >> 1;          // 0..127
    const int lk   = (tid & 1) << 3;    // 0 or 8

    const float* Ap = A + (size_t)(m0 + lrow) * K + lk;
    const float* Bp = B + (size_t)(n0 + lrow) * K + lk;

    float acc[8][8] = {};
    float4 ar0, ar1, br0, br1;

    // Prefetch tile 0
    ar0 = *(const float4*)(Ap + 0);
    ar1 = *(const float4*)(Ap + 4);
    br0 = *(const float4*)(Bp + 0);
    br1 = *(const float4*)(Bp + 4);

    int p = 0;
    As[p][lk+0][lrow] = ar0.x; As[p][lk+1][lrow] = ar0.y;
    As[p][lk+2][lrow] = ar0.z; As[p][lk+3][lrow] = ar0.w;
    As[p][lk+4][lrow] = ar1.x; As[p][lk+5][lrow] = ar1.y;
    As[p][lk+6][lrow] = ar1.z; As[p][lk+7][lrow] = ar1.w;
    Bs[p][lk+0][lrow] = br0.x; Bs[p][lk+1][lrow] = br0.y;
    Bs[p][lk+2][lrow] = br0.z; Bs[p][lk+3][lrow] = br0.w;
    Bs[p][lk+4][lrow] = br1.x; Bs[p][lk+5][lrow] = br1.y;
    Bs[p][lk+6][lrow] = br1.z; Bs[p][lk+7][lrow] = br1.w;
    __syncthreads();

    const int T = K / BK;
    for (int t = 0; t < T; t++) {
        if (t + 1 < T) {
            const float* Ap2 = Ap + (size_t)(t + 1) * BK;
            const float* Bp2 = Bp + (size_t)(t + 1) * BK;
            ar0 = *(const float4*)(Ap2 + 0);
            ar1 = *(const float4*)(Ap2 + 4);
            br0 = *(const float4*)(Bp2 + 0);
            br1 = *(const float4*)(Bp2 + 4);
        }

        #pragma unroll
        for (int k = 0; k < BK; k++) {
            float4 a0 = *(const float4*)&As[p][k][ty * 4];
            float4 a1 = *(const float4*)&As[p][k][64 + ty * 4];
            float4 b0 = *(const float4*)&Bs[p][k][tx * 4];
            float4 b1 = *(const float4*)&Bs[p][k][64 + tx * 4];
            float av[8] = {a0.x, a0.y, a0.z, a0.w, a1.x, a1.y, a1.z, a1.w};
            float bv[8] = {b0.x, b0.y, b0.z, b0.w, b1.x, b1.y, b1.z, b1.w};
            #pragma unroll
            for (int i = 0; i < 8; i++)
                #pragma unroll
                for (int j = 0; j < 8; j++)
                    acc[i][j] += av[i] * bv[j];
        }

        if (t + 1 < T) {
            const int q = p ^ 1;
            As[q][lk+0][lrow] = ar0.x; As[q][lk+1][lrow] = ar0.y;
            As[q][lk+2][lrow] = ar0.z; As[q][lk+3][lrow] = ar0.w;
            As[q][lk+4][lrow] = ar1.x; As[q][lk+5][lrow] = ar1.y;
            As[q][lk+6][lrow] = ar1.z; As[q][lk+7][lrow] = ar1.w;
            Bs[q][lk+0][lrow] = br0.x; Bs[q][lk+1][lrow] = br0.y;
            Bs[q][lk+2][lrow] = br0.z; Bs[q][lk+3][lrow] = br0.w;
            Bs[q][lk+4][lrow] = br1.x; Bs[q][lk+5][lrow] = br1.y;
            Bs[q][lk+6][lrow] = br1.z; Bs[q][lk+7][lrow] = br1.w;
            __syncthreads();
            p = q;
        }
    }

    // Epilogue: 16 float4 stores per thread
    #pragma unroll
    for (int i = 0; i < 8; i++) {
        const int m = m0 + ((i < 4) ? (ty * 4 + i) : (64 + ty * 4 + i - 4));
        #pragma unroll
        for (int half = 0; half < 2; half++) {
            const int n = n0 + half * 64 + tx * 4;
            float4 w = make_float4(acc[i][half*4+0], acc[i][half*4+1],
                                   acc[i][half*4+2], acc[i][half*4+3]);
            if (SCATTER) {
                const int b = m >> 11;           // / SEQ (SEQ=2048)
                const int s = m & (SEQ - 1);
                const int h = n >> 7;
                const int d = n & 127;
                *(float4*)&C[(((size_t)(b * NH + h) * SEQ + s) << 7) + d] = w;
            } else {
                *(float4*)&C[(size_t)m * N + n] = w;
            }
        }
    }
}

// ---------------------------------------------------------------------------
// RoPE (interleaved pairs), in place on a [B, H, S, DKH] tensor.
// pair index i enumerates (b, h, s, half) with half fastest; elem = 2*i.
// ---------------------------------------------------------------------------
__global__ __launch_bounds__(256) void rope_kernel(
    float* __restrict__ T, const int* __restrict__ pos)
{
    const int i = blockIdx.x * blockDim.x + threadIdx.x;
    const int half = i & 63;                 // 0..63
    const int s    = (i >> 6) & (SEQ - 1);
    const int bh   = i >> 17;                // / (64*2048)
    const int b    = bh >> 4;                // / NH
    const float p  = (float)pos[b * SEQ + s];
    // inv_freq = theta^(-2*half/128) = exp(-half * ln(10000)/64)
    const float ang = p * expf(-(float)half * (9.210340371976184f / 64.0f));
    float sn, cs;
    sincosf(ang, &sn, &cs);
    float2 v = *(float2*)(T + ((size_t)i << 1));
    float2 r;
    r.x = v.x * cs - v.y * sn;
    r.y = v.x * sn + v.y * cs;
    *(float2*)(T + ((size_t)i << 1)) = r;
}

// ---------------------------------------------------------------------------
// Flash attention, causal. One CTA = 64 q rows of one (b,h).
// smem tiles padded to stride 132 (16B-aligned, bank-friendly with the
// strided column ownership below). Column ownership: c_j = tx + 16*j so K
// reads are <=2-way conflicted and Ps/V accesses are conflict-free.
// ---------------------------------------------------------------------------
__global__ __launch_bounds__(256) void flash_kernel(
    const float* __restrict__ Q, const float* __restrict__ K,
    const float* __restrict__ V, float* __restrict__ AO)
{
    constexpr int BQ = 64, BKV = 64, LDSW = 132;
    extern __shared__ float sm[];
    float* Qs = sm;                      // [64][132]
    float* Ks = Qs + BQ * LDSW;          // [64][132]
    float* Vs = Ks + BKV * LDSW;         // [64][132]
    float* Ps = Vs + BKV * LDSW;         // [64][64]

    const int qb = blockIdx.x, bh = blockIdx.y;
    const int b = bh >> 4, h = bh & 15;
    const float* Qg = Q + ((size_t)bh * SEQ + (size_t)qb * BQ) * DKH;
    const float* Kg = K + (size_t)bh * SEQ * DKH;
    const float* Vg = V + (size_t)bh * SEQ * DKH;

    const int tid = threadIdx.x, tx = tid & 15, ty = tid >> 4;

    // Load Q tile (2048 float4s across 256 threads)
    #pragma unroll
    for (int it = 0; it < 8; it++) {
        int idx = tid + it * 256;
        int r = idx >> 5, c = (idx & 31) << 2;
        *(float4*)&Qs[r * LDSW + c] = *(const float4*)&Qg[r * DKH + c];
    }

    float m_i[4], l_i[4], o[4][8];
    #pragma unroll
    for (int i = 0; i < 4; i++) {
        m_i[i] = -INFINITY; l_i[i] = 0.0f;
        #pragma unroll
        for (int c = 0; c < 8; c++) o[i][c] = 0.0f;
    }

    const float SCALE = 0.08838834764831845f; // 1/sqrt(128)

    for (int kb = 0; kb <= qb; kb++) {
        __syncthreads();  // prior-iter Vs/Ps reads done; Qs load visible
        const float* Kt = Kg + (size_t)kb * BKV * DKH;
        const float* Vt = Vg + (size_t)kb * BKV * DKH;
        #pragma unroll
        for (int it = 0; it < 8; it++) {
            int idx = tid + it * 256;
            int r = idx >> 5, c = (idx & 31) << 2;
            *(float4*)&Ks[r * LDSW + c] = *(const float4*)&Kt[r * DKH + c];
            *(float4*)&Vs[r * LDSW + c] = *(const float4*)&Vt[r * DKH + c];
        }
        __syncthreads();

        // S = Q K^T : rows ty*4+i, cols tx + 16*j
        float s[4][4] = {};
        #pragma unroll 4
        for (int d = 0; d < DKH; d++) {
            float q0 = Qs[(ty * 4 + 0) * LDSW + d];
            float q1 = Qs[(ty * 4 + 1) * LDSW + d];
            float q2 = Qs[(ty * 4 + 2) * LDSW + d];
            float q3 = Qs[(ty * 4 + 3) * LDSW + d];
            float k0 = Ks[(tx + 0)  * LDSW + d];
            float k1 = Ks[(tx + 16) * LDSW + d];
            float k2 = Ks[(tx + 32) * LDSW + d];
            float k3 = Ks[(tx + 48) * LDSW + d];
            s[0][0] += q0*k0; s[0][1] += q0*k1; s[0][2] += q0*k2; s[0][3] += q0*k3;
            s[1][0] += q1*k0; s[1][1] += q1*k1; s[1][2] += q1*k2; s[1][3] += q1*k3;
            s[2][0] += q2*k0; s[2][1] += q2*k1; s[2][2] += q2*k2; s[2][3] += q2*k3;
            s[3][0] += q3*k0; s[3][1] += q3*k1; s[3][2] += q3*k2; s[3][3] += q3*k3;
        }

        const bool diag = (kb == qb);
        #pragma unroll
        for (int i = 0; i < 4; i++) {
            #pragma unroll
            for (int j = 0; j < 4; j++) {
                s[i][j] *= SCALE;
                if (diag && (tx + 16 * j) > (ty * 4 + i)) s[i][j] = -1e30f;
            }
        }

        // Online softmax stats (16-lane groups share a row set)
        #pragma unroll
        for (int i = 0; i < 4; i++) {
            float rmax = fmaxf(fmaxf(s[i][0], s[i][1]), fmaxf(s[i][2], s[i][3]));
            rmax = fmaxf(rmax, __shfl_xor_sync(0xffffffffu, rmax, 1));
            rmax = fmaxf(rmax, __shfl_xor_sync(0xffffffffu, rmax, 2));
            rmax = fmaxf(rmax, __shfl_xor_sync(0xffffffffu, rmax, 4));
            rmax = fmaxf(rmax, __shfl_xor_sync(0xffffffffu, rmax, 8));
            float mnew  = fmaxf(m_i[i], rmax);
            float alpha = expf(m_i[i] - mnew);
            float p0 = expf(s[i][0] - mnew);
            float p1 = expf(s[i][1] - mnew);
            float p2 = expf(s[i][2] - mnew);
            float p3 = expf(s[i][3] - mnew);
            float rsum = p0 + p1 + p2 + p3;
            rsum += __shfl_xor_sync(0xffffffffu, rsum, 1);
            rsum += __shfl_xor_sync(0xffffffffu, rsum, 2);
            rsum += __shfl_xor_sync(0xffffffffu, rsum, 4);
            rsum += __shfl_xor_sync(0xffffffffu, rsum, 8);
            l_i[i] = l_i[i] * alpha + rsum;
            m_i[i] = mnew;
            #pragma unroll
            for (int c = 0; c < 8; c++) o[i][c] *= alpha;
            int r = ty * 4 + i;
            Ps[r * 64 + tx +  0] = p0;
            Ps[r * 64 + tx + 16] = p1;
            Ps[r * 64 + tx + 32] = p2;
            Ps[r * 64 + tx + 48] = p3;
        }
        __syncthreads();

        // O += P V : O cols tx + 16*cc
        #pragma unroll 2
        for (int j = 0; j < BKV; j++) {
            float v[8];
            #pragma unroll
            for (int cc = 0; cc < 8; cc++) v[cc] = Vs[j * LDSW + tx + 16 * cc];
            #pragma unroll
            for (int i = 0; i < 4; i++) {
                float p = Ps[(ty * 4 + i) * 64 + j];
                #pragma unroll
                for (int cc = 0; cc < 8; cc++) o[i][cc] += p * v[cc];
            }
        }
    }

    // Epilogue: normalize, write to [b, s, h*128 + c] layout (for output proj)
    #pragma unroll
    for (int i = 0; i < 4; i++) {
        float inv = 1.0f / l_i[i];
        int srow = qb * BQ + ty * 4 + i;
        float* dst = AO + (size_t)(b * SEQ + srow) * D_MODEL + h * DKH;
        #pragma unroll
        for (int cc = 0; cc < 8; cc++) dst[tx + 16 * cc] = o[i][cc] * inv;
    }
}

// ---------------------------------------------------------------------------
extern "C" void kernel_launch(void* const* d_in, const int* in_sizes, int n_in,
                              void* d_out, int out_size)
{
    const float* x   = (const float*)d_in[0];
    const int*   pos = (const int*)  d_in[1];
    const float* Wq  = (const float*)d_in[2];
    const float* Wk  = (const float*)d_in[3];
    const float* Wv  = (const float*)d_in[4];
    const float* Wo  = (const float*)d_in[5];
    float* out = (float*)d_out;

    float *qp, *kp, *vp, *aop;
    cudaGetSymbolAddress((void**)&qp,  g_Q);
    cudaGetSymbolAddress((void**)&kp,  g_K);
    cudaGetSymbolAddress((void**)&vp,  g_V);
    cudaGetSymbolAddress((void**)&aop, g_AO);

    dim3 gProj(D_MODEL / 128, MTOT / 128);  // (16, 32) = 512 CTAs
    gemm_abt_kernel<1><<<gProj, 256>>>(x, Wq, qp, MTOT, D_MODEL, D_MODEL);
    gemm_abt_kernel<1><<<gProj, 256>>>(x, Wk, kp, MTOT, D_MODEL, D_MODEL);
    gemm_abt_kernel<1><<<gProj, 256>>>(x, Wv, vp, MTOT, D_MODEL, D_MODEL);

    const int npairs = BATCH * NH * SEQ * (DKH / 2);  // 4,194,304
    rope_kernel<<<npairs / 256, 256>>>(qp, pos);
    rope_kernel<<<npairs / 256, 256>>>(kp, pos);

    const int flash_smem = (3 * 64 * 132 + 64 * 64) * (int)sizeof(float);  // 117,760 B
    cudaFuncSetAttribute(flash_kernel, cudaFuncAttributeMaxDynamicSharedMemorySize, flash_smem);
    dim3 gFlash(SEQ / 64, BATCH * NH);    // (32, 32)
    flash_kernel<<<gFlash, 256, flash_smem>>>(qp, kp, vp, aop);

    gemm_abt_kernel<0><<<gProj, 256>>>(aop, Wo, out, MTOT, D_MODEL, D_MODEL);
}

// round 11
// speedup vs baseline: 1.2586x; 1.2586x over previous
#include <cuda_runtime.h>
#include <cuda_bf16.h>
#include <math.h>
#include <stdint.h>

#define D_MODEL 2048
#define NH      16
#define DKH     128
#define BATCH   2
#define SEQ     2048
#define MTOT    (BATCH*SEQ)   // 4096

// ---------------- scratch (__device__ globals; no allocation allowed) ------
__device__ float g_Q[(size_t)BATCH*NH*SEQ*DKH];
__device__ float g_K[(size_t)BATCH*NH*SEQ*DKH];
__device__ float g_V[(size_t)BATCH*NH*SEQ*DKH];
__device__ float g_AO[(size_t)MTOT*D_MODEL];

__device__ __nv_bfloat16 g_x_hi[(size_t)MTOT*D_MODEL];
__device__ __nv_bfloat16 g_x_lo[(size_t)MTOT*D_MODEL];
__device__ __nv_bfloat16 g_ao_hi[(size_t)MTOT*D_MODEL];
__device__ __nv_bfloat16 g_ao_lo[(size_t)MTOT*D_MODEL];
__device__ __nv_bfloat16 g_Wq_hi[(size_t)D_MODEL*D_MODEL];
__device__ __nv_bfloat16 g_Wq_lo[(size_t)D_MODEL*D_MODEL];
__device__ __nv_bfloat16 g_Wk_hi[(size_t)D_MODEL*D_MODEL];
__device__ __nv_bfloat16 g_Wk_lo[(size_t)D_MODEL*D_MODEL];
__device__ __nv_bfloat16 g_Wv_hi[(size_t)D_MODEL*D_MODEL];
__device__ __nv_bfloat16 g_Wv_lo[(size_t)D_MODEL*D_MODEL];
__device__ __nv_bfloat16 g_Wo_hi[(size_t)D_MODEL*D_MODEL];
__device__ __nv_bfloat16 g_Wo_lo[(size_t)D_MODEL*D_MODEL];

// ---------------------------------------------------------------------------
// Split fp32 -> bf16 hi + bf16 lo (residual). n4 = n/4.
// ---------------------------------------------------------------------------
__global__ __launch_bounds__(256) void split_kernel(
    const float* __restrict__ src, __nv_bfloat16* __restrict__ hi,
    __nv_bfloat16* __restrict__ lo, int n4)
{
    int i = blockIdx.x * blockDim.x + threadIdx.x;
    if (i >= n4) return;
    float4 v = ((const float4*)src)[i];
    float vv[4] = {v.x, v.y, v.z, v.w};
    __nv_bfloat16 h[4], l[4];
    #pragma unroll
    for (int j = 0; j < 4; j++) {
        h[j] = __float2bfloat16(vv[j]);
        l[j] = __float2bfloat16(vv[j] - __bfloat162float(h[j]));
    }
    ((__nv_bfloat162*)hi)[2*i+0] = __nv_bfloat162{h[0], h[1]};
    ((__nv_bfloat162*)hi)[2*i+1] = __nv_bfloat162{h[2], h[3]};
    ((__nv_bfloat162*)lo)[2*i+0] = __nv_bfloat162{l[0], l[1]};
    ((__nv_bfloat162*)lo)[2*i+1] = __nv_bfloat162{l[2], l[3]};
}

// ---------------------------------------------------------------------------
// mma.sync bf16 split GEMM (baseline-ISA tensor cores; NO tcgen05):
// C[m,n] = sum_k A[m,k]*B[n,k] in ~fp32 precision via hi*hi + hi*lo + lo*hi.
// CTA tile 128x128x32, 8 warps (2m x 4n), warp tile 64x32, double-buffered
// padded smem (stride 40 bf16 -> conflict-free fragment loads), fp32 acc.
// SCATTER=1: write into [b,h,s,d] (one head per 128-wide n-tile).
// ---------------------------------------------------------------------------
template<int SCATTER>
__global__ __launch_bounds__(256) void mma_gemm_kernel(
    const __nv_bfloat16* __restrict__ Ah, const __nv_bfloat16* __restrict__ Al,
    const __nv_bfloat16* __restrict__ Bh, const __nv_bfloat16* __restrict__ Bl,
    float* __restrict__ C)
{
    constexpr int BM = 128, BN = 128, BK = 32, KTOT = 2048, LDT = 40;
    constexpr int CHUNKS = KTOT / BK;        // 64 per pass
    constexpr int NITER  = 3 * CHUNKS;       // 192

    __shared__ __nv_bfloat16 As[2][BM * LDT];   // 2 x 10,240 B
    __shared__ __nv_bfloat16 Bs[2][BN * LDT];   // 2 x 10,240 B

    const int tid  = threadIdx.x;
    const int lane = tid & 31;
    const int wid  = tid >> 5;
    const int wm   = wid & 1;      // 0..1  (64-row half)
    const int wn   = wid >> 1;     // 0..3  (32-col quarter)
    const int m0 = blockIdx.y * BM, n0 = blockIdx.x * BN;

    // Loader mapping: each thread owns one row, 16 contiguous bf16.
    const int lrow = tid >> 1;            // 0..127
    const int lseg = (tid & 1) * 16;      // 0 or 16 (bf16 offset)

    float acc[4][4][4];
    #pragma unroll
    for (int mi = 0; mi < 4; mi++)
        #pragma unroll
        for (int ni = 0; ni < 4; ni++)
            #pragma unroll
            for (int r = 0; r < 4; r++) acc[mi][ni][r] = 0.0f;

    // Prefetch chunk 0 (pass 0: Ah, Bh)
    uint4 apre[2], bpre[2];
    {
        const __nv_bfloat16* ap = Ah + (size_t)(m0 + lrow) * KTOT + lseg;
        const __nv_bfloat16* bp = Bh + (size_t)(n0 + lrow) * KTOT + lseg;
        apre[0] = *(const uint4*)(ap);     apre[1] = *(const uint4*)(ap + 8);
        bpre[0] = *(const uint4*)(bp);     bpre[1] = *(const uint4*)(bp + 8);
    }
    int p = 0;
    *(uint4*)&As[p][lrow * LDT + lseg]     = apre[0];
    *(uint4*)&As[p][lrow * LDT + lseg + 8] = apre[1];
    *(uint4*)&Bs[p][lrow * LDT + lseg]     = bpre[0];
    *(uint4*)&Bs[p][lrow * LDT + lseg + 8] = bpre[1];
    __syncthreads();

    const int r0 = lane >> 2;          // 0..7
    const int kq = (lane & 3) * 2;     // 0,2,4,6

    for (int c = 0; c < NITER; c++) {
        // Prefetch next chunk into registers (overlaps MMA)
        if (c + 1 < NITER) {
            const int pass = (c + 1) >> 6;
            const int kc   = ((c + 1) & (CHUNKS - 1)) * BK;
            const __nv_bfloat16* Asrc = (pass == 2) ? Al : Ah;
            const __nv_bfloat16* Bsrc = (pass == 1) ? Bl : Bh;
            const __nv_bfloat16* ap = Asrc + (size_t)(m0 + lrow) * KTOT + kc + lseg;
            const __nv_bfloat16* bp = Bsrc + (size_t)(n0 + lrow) * KTOT + kc + lseg;
            apre[0] = *(const uint4*)(ap);     apre[1] = *(const uint4*)(ap + 8);
            bpre[0] = *(const uint4*)(bp);     bpre[1] = *(const uint4*)(bp + 8);
        }

        // Compute on buffer p: 2 k-steps of 16
        #pragma unroll
        for (int kk = 0; kk < BK; kk += 16) {
            uint32_t a[4][4], b[4][2];
            #pragma unroll
            for (int mi = 0; mi < 4; mi++) {
                const __nv_bfloat16* base =
                    &As[p][(wm * 64 + mi * 16 + r0) * LDT + kk + kq];
                a[mi][0] = *(const uint32_t*)(base);
                a[mi][1] = *(const uint32_t*)(base + 8 * LDT);
                a[mi][2] = *(const uint32_t*)(base + 8);
                a[mi][3] = *(const uint32_t*)(base + 8 * LDT + 8);
            }
            #pragma unroll
            for (int ni = 0; ni < 4; ni++) {
                const __nv_bfloat16* base =
                    &Bs[p][(wn * 32 + ni * 8 + r0) * LDT + kk + kq];
                b[ni][0] = *(const uint32_t*)(base);
                b[ni][1] = *(const uint32_t*)(base + 8);
            }
            #pragma unroll
            for (int mi = 0; mi < 4; mi++)
                #pragma unroll
                for (int ni = 0; ni < 4; ni++) {
                    asm volatile(
                        "mma.sync.aligned.m16n8k16.row.col.f32.bf16.bf16.f32 "
                        "{%0,%1,%2,%3}, {%4,%5,%6,%7}, {%8,%9}, {%0,%1,%2,%3};"
                        : "+f"(acc[mi][ni][0]), "+f"(acc[mi][ni][1]),
                          "+f"(acc[mi][ni][2]), "+f"(acc[mi][ni][3])
                        : "r"(a[mi][0]), "r"(a[mi][1]), "r"(a[mi][2]), "r"(a[mi][3]),
                          "r"(b[ni][0]), "r"(b[ni][1]));
                }
        }

        // Store prefetched chunk into the other buffer
        if (c + 1 < NITER) {
            const int q = p ^ 1;
            *(uint4*)&As[q][lrow * LDT + lseg]     = apre[0];
            *(uint4*)&As[q][lrow * LDT + lseg + 8] = apre[1];
            *(uint4*)&Bs[q][lrow * LDT + lseg]     = bpre[0];
            *(uint4*)&Bs[q][lrow * LDT + lseg + 8] = bpre[1];
            __syncthreads();
            p = q;
        }
    }

    // Epilogue: c0,c1 -> (row, col+0/1); c2,c3 -> (row+8, col+0/1)
    #pragma unroll
    for (int mi = 0; mi < 4; mi++) {
        #pragma unroll
        for (int half = 0; half < 2; half++) {
            const int m = m0 + wm * 64 + mi * 16 + r0 + half * 8;
            const int bb = m >> 11;           // / SEQ
            const int s  = m & (SEQ - 1);
            #pragma unroll
            for (int ni = 0; ni < 4; ni++) {
                const int n = n0 + wn * 32 + ni * 8 + kq;
                float2 w = make_float2(acc[mi][ni][half*2+0], acc[mi][ni][half*2+1]);
                if (SCATTER) {
                    const int h = n >> 7;
                    const int d = n & 127;
                    *(float2*)&C[(((size_t)(bb * NH + h) * SEQ + s) << 7) + d] = w;
                } else {
                    *(float2*)&C[(size_t)m * D_MODEL + n] = w;
                }
            }
        }
    }
}

// ---------------------------------------------------------------------------
// RoPE (interleaved pairs), in place on a [B, H, S, DKH] tensor.
// ---------------------------------------------------------------------------
__global__ __launch_bounds__(256) void rope_kernel(
    float* __restrict__ T, const int* __restrict__ pos)
{
    const int i = blockIdx.x * blockDim.x + threadIdx.x;
    const int half = i & 63;
    const int s    = (i >> 6) & (SEQ - 1);
    const int bh   = i >> 17;
    const int b    = bh >> 4;
    const float p  = (float)pos[b * SEQ + s];
    const float ang = p * expf(-(float)half * (9.210340371976184f / 64.0f));
    float sn, cs;
    sincosf(ang, &sn, &cs);
    float2 v = *(float2*)(T + ((size_t)i << 1));
    float2 r;
    r.x = v.x * cs - v.y * sn;
    r.y = v.x * sn + v.y * cs;
    *(float2*)(T + ((size_t)i << 1)) = r;
}

// ---------------------------------------------------------------------------
// Flash attention, causal, fp32 (unchanged from round-4 passing kernel).
// ---------------------------------------------------------------------------
__global__ __launch_bounds__(256) void flash_kernel(
    const float* __restrict__ Q, const float* __restrict__ K,
    const float* __restrict__ V, float* __restrict__ AO)
{
    constexpr int BQ = 64, BKV = 64, LDSW = 132;
    extern __shared__ float sm[];
    float* Qs = sm;
    float* Ks = Qs + BQ * LDSW;
    float* Vs = Ks + BKV * LDSW;
    float* Ps = Vs + BKV * LDSW;

    const int qb = blockIdx.x, bh = blockIdx.y;
    const int b = bh >> 4, h = bh & 15;
    const float* Qg = Q + ((size_t)bh * SEQ + (size_t)qb * BQ) * DKH;
    const float* Kg = K + (size_t)bh * SEQ * DKH;
    const float* Vg = V + (size_t)bh * SEQ * DKH;

    const int tid = threadIdx.x, tx = tid & 15, ty = tid >> 4;

    #pragma unroll
    for (int it = 0; it < 8; it++) {
        int idx = tid + it * 256;
        int r = idx >> 5, c = (idx & 31) << 2;
        *(float4*)&Qs[r * LDSW + c] = *(const float4*)&Qg[r * DKH + c];
    }

    float m_i[4], l_i[4], o[4][8];
    #pragma unroll
    for (int i = 0; i < 4; i++) {
        m_i[i] = -INFINITY; l_i[i] = 0.0f;
        #pragma unroll
        for (int c = 0; c < 8; c++) o[i][c] = 0.0f;
    }

    const float SCALE = 0.08838834764831845f;

    for (int kb = 0; kb <= qb; kb++) {
        __syncthreads();
        const float* Kt = Kg + (size_t)kb * BKV * DKH;
        const float* Vt = Vg + (size_t)kb * BKV * DKH;
        #pragma unroll
        for (int it = 0; it < 8; it++) {
            int idx = tid + it * 256;
            int r = idx >> 5, c = (idx & 31) << 2;
            *(float4*)&Ks[r * LDSW + c] = *(const float4*)&Kt[r * DKH + c];
            *(float4*)&Vs[r * LDSW + c] = *(const float4*)&Vt[r * DKH + c];
        }
        __syncthreads();

        float s[4][4] = {};
        #pragma unroll 4
        for (int d = 0; d < DKH; d++) {
            float q0 = Qs[(ty * 4 + 0) * LDSW + d];
            float q1 = Qs[(ty * 4 + 1) * LDSW + d];
            float q2 = Qs[(ty * 4 + 2) * LDSW + d];
            float q3 = Qs[(ty * 4 + 3) * LDSW + d];
            float k0 = Ks[(tx + 0)  * LDSW + d];
            float k1 = Ks[(tx + 16) * LDSW + d];
            float k2 = Ks[(tx + 32) * LDSW + d];
            float k3 = Ks[(tx + 48) * LDSW + d];
            s[0][0] += q0*k0; s[0][1] += q0*k1; s[0][2] += q0*k2; s[0][3] += q0*k3;
            s[1][0] += q1*k0; s[1][1] += q1*k1; s[1][2] += q1*k2; s[1][3] += q1*k3;
            s[2][0] += q2*k0; s[2][1] += q2*k1; s[2][2] += q2*k2; s[2][3] += q2*k3;
            s[3][0] += q3*k0; s[3][1] += q3*k1; s[3][2] += q3*k2; s[3][3] += q3*k3;
        }

        const bool diag = (kb == qb);
        #pragma unroll
        for (int i = 0; i < 4; i++) {
            #pragma unroll
            for (int j = 0; j < 4; j++) {
                s[i][j] *= SCALE;
                if (diag && (tx + 16 * j) > (ty * 4 + i)) s[i][j] = -1e30f;
            }
        }

        #pragma unroll
        for (int i = 0; i < 4; i++) {
            float rmax = fmaxf(fmaxf(s[i][0], s[i][1]), fmaxf(s[i][2], s[i][3]));
            rmax = fmaxf(rmax, __shfl_xor_sync(0xffffffffu, rmax, 1));
            rmax = fmaxf(rmax, __shfl_xor_sync(0xffffffffu, rmax, 2));
            rmax = fmaxf(rmax, __shfl_xor_sync(0xffffffffu, rmax, 4));
            rmax = fmaxf(rmax, __shfl_xor_sync(0xffffffffu, rmax, 8));
            float mnew  = fmaxf(m_i[i], rmax);
            float alpha = expf(m_i[i] - mnew);
            float p0 = expf(s[i][0] - mnew);
            float p1 = expf(s[i][1] - mnew);
            float p2 = expf(s[i][2] - mnew);
            float p3 = expf(s[i][3] - mnew);
            float rsum = p0 + p1 + p2 + p3;
            rsum += __shfl_xor_sync(0xffffffffu, rsum, 1);
            rsum += __shfl_xor_sync(0xffffffffu, rsum, 2);
            rsum += __shfl_xor_sync(0xffffffffu, rsum, 4);
            rsum += __shfl_xor_sync(0xffffffffu, rsum, 8);
            l_i[i] = l_i[i] * alpha + rsum;
            m_i[i] = mnew;
            #pragma unroll
            for (int c = 0; c < 8; c++) o[i][c] *= alpha;
            int r = ty * 4 + i;
            Ps[r * 64 + tx +  0] = p0;
            Ps[r * 64 + tx + 16] = p1;
            Ps[r * 64 + tx + 32] = p2;
            Ps[r * 64 + tx + 48] = p3;
        }
        __syncthreads();

        #pragma unroll 2
        for (int j = 0; j < BKV; j++) {
            float v[8];
            #pragma unroll
            for (int cc = 0; cc < 8; cc++) v[cc] = Vs[j * LDSW + tx + 16 * cc];
            #pragma unroll
            for (int i = 0; i < 4; i++) {
                float p = Ps[(ty * 4 + i) * 64 + j];
                #pragma unroll
                for (int cc = 0; cc < 8; cc++) o[i][cc] += p * v[cc];
            }
        }
    }

    #pragma unroll
    for (int i = 0; i < 4; i++) {
        float inv = 1.0f / l_i[i];
        int srow = qb * BQ + ty * 4 + i;
        float* dst = AO + (size_t)(b * SEQ + srow) * D_MODEL + h * DKH;
        #pragma unroll
        for (int cc = 0; cc < 8; cc++) dst[tx + 16 * cc] = o[i][cc] * inv;
    }
}

// ---------------------------------------------------------------------------
extern "C" void kernel_launch(void* const* d_in, const int* in_sizes, int n_in,
                              void* d_out, int out_size)
{
    const float* x   = (const float*)d_in[0];
    const int*   pos = (const int*)  d_in[1];
    const float* Wq  = (const float*)d_in[2];
    const float* Wk  = (const float*)d_in[3];
    const float* Wv  = (const float*)d_in[4];
    const float* Wo  = (const float*)d_in[5];
    float* out = (float*)d_out;

    float *qp, *kp, *vp, *aop;
    cudaGetSymbolAddress((void**)&qp,  g_Q);
    cudaGetSymbolAddress((void**)&kp,  g_K);
    cudaGetSymbolAddress((void**)&vp,  g_V);
    cudaGetSymbolAddress((void**)&aop, g_AO);
    __nv_bfloat16 *xh, *xl, *aoh, *aol;
    __nv_bfloat16 *wqh, *wql, *wkh, *wkl, *wvh, *wvl, *woh, *wol;
    cudaGetSymbolAddress((void**)&xh,  g_x_hi);  cudaGetSymbolAddress((void**)&xl,  g_x_lo);
    cudaGetSymbolAddress((void**)&aoh, g_ao_hi); cudaGetSymbolAddress((void**)&aol, g_ao_lo);
    cudaGetSymbolAddress((void**)&wqh, g_Wq_hi); cudaGetSymbolAddress((void**)&wql, g_Wq_lo);
    cudaGetSymbolAddress((void**)&wkh, g_Wk_hi); cudaGetSymbolAddress((void**)&wkl, g_Wk_lo);
    cudaGetSymbolAddress((void**)&wvh, g_Wv_hi); cudaGetSymbolAddress((void**)&wvl, g_Wv_lo);
    cudaGetSymbolAddress((void**)&woh, g_Wo_hi); cudaGetSymbolAddress((void**)&wol, g_Wo_lo);

    // Split conversions
    const int nx4 = MTOT * D_MODEL / 4;       // 2,097,152
    const int nw4 = D_MODEL * D_MODEL / 4;    // 1,048,576
    split_kernel<<<nx4 / 256, 256>>>(x,  xh,  xl,  nx4);
    split_kernel<<<nw4 / 256, 256>>>(Wq, wqh, wql, nw4);
    split_kernel<<<nw4 / 256, 256>>>(Wk, wkh, wkl, nw4);
    split_kernel<<<nw4 / 256, 256>>>(Wv, wvh, wvl, nw4);
    split_kernel<<<nw4 / 256, 256>>>(Wo, woh, wol, nw4);

    // Tensor-core projection GEMMs (mma.sync, static smem)
    dim3 gGemm(D_MODEL / 128, MTOT / 128);    // (16, 32)
    mma_gemm_kernel<1><<<gGemm, 256>>>(xh, xl, wqh, wql, qp);
    mma_gemm_kernel<1><<<gGemm, 256>>>(xh, xl, wkh, wkl, kp);
    mma_gemm_kernel<1><<<gGemm, 256>>>(xh, xl, wvh, wvl, vp);

    // RoPE
    const int npairs = BATCH * NH * SEQ * (DKH / 2);
    rope_kernel<<<npairs / 256, 256>>>(qp, pos);
    rope_kernel<<<npairs / 256, 256>>>(kp, pos);

    // Flash attention (fp32)
    const int flash_smem = (3 * 64 * 132 + 64 * 64) * (int)sizeof(float);
    cudaFuncSetAttribute(flash_kernel, cudaFuncAttributeMaxDynamicSharedMemorySize, flash_smem);
    dim3 gFlash(SEQ / 64, BATCH * NH);
    flash_kernel<<<gFlash, 256, flash_smem>>>(qp, kp, vp, aop);

    // Output projection
    split_kernel<<<nx4 / 256, 256>>>(aop, aoh, aol, nx4);
    mma_gemm_kernel<0><<<gGemm, 256>>>(aoh, aol, woh, wol, out);
}